// round 12
// baseline (speedup 1.0000x reference)
#include <cuda_runtime.h>
#include <math.h>

// ---------------------------------------------------------------------------
// RefEncoder: 4x stride-2 3x3 convs (SAME pad = 0 before / 1 after), gelu(tanh)
// on first three, then per-group query proj + codebook-key proj + argmax.
// ---------------------------------------------------------------------------

#define NIMG 16

__device__ float g_buf1[NIMG * 64 * 128 * 128];   // conv1 out (gelu)
__device__ float g_buf2[NIMG * 128 * 64 * 64];    // conv2 out (gelu)
__device__ float g_buf3[NIMG * 256 * 32 * 32];    // conv3 out (gelu)
__device__ float g_buf4[NIMG * 256 * 16 * 16];    // conv4 out (latent)
__device__ float g_kprojT[4 * 64 * 256];          // kproj transposed [m][c][k]

__device__ __forceinline__ float gelu_tanh(float x) {
    float x3 = x * x * x;
    float t = tanhf(0.7978845608028654f * (x + 0.044715f * x3));
    return 0.5f * x * (1.0f + t);
}

// ---------------------------------------------------------------------------
// conv1: Cin=3, Cout=64, 256 -> 128, normalize input (2x-1), gelu output.
// ---------------------------------------------------------------------------
__global__ __launch_bounds__(256) void conv1_kernel(
    const float* __restrict__ x, const float* __restrict__ w,
    const float* __restrict__ b)
{
    const int HIN = 256, HOUT = 128;
    __shared__ float sIn[3][17][18];
    __shared__ __align__(16) float sW[3][9][64];

    int n = blockIdx.z;
    int tiles_x = HOUT / 8;
    int ty = blockIdx.x / tiles_x;
    int txo = blockIdx.x % tiles_x;
    int oy0 = ty * 8, ox0 = txo * 8;
    int tid = threadIdx.x;

    for (int idx = tid; idx < 1728; idx += 256) {
        int oc = idx / 27, r = idx % 27;
        int ic = r / 9, kk = r % 9;
        sW[ic][kk][oc] = w[idx];
    }
    for (int idx = tid; idx < 3 * 17 * 17; idx += 256) {
        int ic = idx / 289, r2 = idx % 289;
        int r = r2 / 17, c = r2 % 17;
        int iy = oy0 * 2 + r, ix = ox0 * 2 + c;
        float v = 0.0f;
        if (iy < HIN && ix < HIN)
            v = 2.0f * x[((n * 3 + ic) * HIN + iy) * HIN + ix] - 1.0f;
        sIn[ic][r][c] = v;
    }
    __syncthreads();

    int ocq = (tid & 15) * 4;
    int sp = (tid >> 4) * 4;
    int oy = sp >> 3, oxl = sp & 7;

    float acc[4][4];
#pragma unroll
    for (int j = 0; j < 4; j++)
#pragma unroll
        for (int q = 0; q < 4; q++) acc[j][q] = 0.0f;

#pragma unroll
    for (int ic = 0; ic < 3; ic++) {
#pragma unroll
        for (int kk = 0; kk < 9; kk++) {
            float4 wv = *(const float4*)&sW[ic][kk][ocq];
#pragma unroll
            for (int j = 0; j < 4; j++) {
                float iv = sIn[ic][oy * 2 + kk / 3][(oxl + j) * 2 + kk % 3];
                acc[j][0] = fmaf(iv, wv.x, acc[j][0]);
                acc[j][1] = fmaf(iv, wv.y, acc[j][1]);
                acc[j][2] = fmaf(iv, wv.z, acc[j][2]);
                acc[j][3] = fmaf(iv, wv.w, acc[j][3]);
            }
        }
    }
#pragma unroll
    for (int j = 0; j < 4; j++)
#pragma unroll
        for (int q = 0; q < 4; q++) {
            int oc = ocq + q;
            float v = acc[j][q] + b[oc];
            g_buf1[((n * 64 + oc) * HOUT + oy0 + oy) * HOUT + ox0 + oxl + j] =
                gelu_tanh(v);
        }
}

// ---------------------------------------------------------------------------
// convR: register-blocked stride-2 3x3 conv (R6's best for conv2/3).
// CTA: 256 threads, tile = 64 oc x (8 rows x 16 cols). Thread: 4 oc x 8 px,
// float2 reuse across kx (kk = ky*3+kx ascending -> bit-identical order).
// ---------------------------------------------------------------------------
template <int CIN, int COUT, int HIN, int HOUT, bool DO_GELU>
__global__ __launch_bounds__(256) void convR_kernel(
    const float* __restrict__ in, const float* __restrict__ w,
    const float* __restrict__ b, float* __restrict__ out)
{
    __shared__ __align__(16) float sIn[8][17][34];   // 33 cols used (+1 pad)
    __shared__ __align__(16) float sW[8][9][64];

    int n = blockIdx.z;
    int oc0 = blockIdx.y * 64;
    const int tiles_x = HOUT / 16;
    int ty = (tiles_x > 1) ? ((int)blockIdx.x / tiles_x) : (int)blockIdx.x;
    int txo = (tiles_x > 1) ? ((int)blockIdx.x % tiles_x) : 0;
    int oy0 = ty * 8, ox0 = txo * 16;
    int tid = threadIdx.x;

    int ocq = (tid & 15) * 4;
    int sp = tid >> 4;                               // 0..15
    int oy = sp >> 1;                                // 0..7
    int ox8 = (sp & 1) * 8;                          // 0 or 8

    float acc[8][4];
#pragma unroll
    for (int j = 0; j < 8; j++)
#pragma unroll
        for (int q = 0; q < 4; q++) acc[j][q] = 0.0f;

    for (int ic0 = 0; ic0 < CIN; ic0 += 8) {
        __syncthreads();
        for (int idx = tid; idx < 4608; idx += 256) {
            int oc = idx / 72, r = idx % 72;
            int ic = r / 9, kk = r % 9;
            sW[ic][kk][oc] = w[(oc0 + oc) * (CIN * 9) + (ic0 + ic) * 9 + kk];
        }
        for (int idx = tid; idx < 8 * 17 * 33; idx += 256) {
            int ic = idx / 561;
            int rem = idx - ic * 561;
            int r = rem / 33, c = rem - r * 33;
            int iy = oy0 * 2 + r, ix = ox0 * 2 + c;
            float v = 0.0f;
            if (iy < HIN && ix < HIN)
                v = in[((n * CIN + ic0 + ic) * HIN + iy) * HIN + ix];
            sIn[ic][r][c] = v;
        }
        __syncthreads();

#pragma unroll
        for (int ic = 0; ic < 8; ic++) {
#pragma unroll
            for (int ky = 0; ky < 3; ky++) {
                const float* row = &sIn[ic][oy * 2 + ky][2 * ox8];
                float2 rv[9];
#pragma unroll
                for (int i = 0; i < 9; i++)
                    rv[i] = *(const float2*)(row + 2 * i);
#pragma unroll
                for (int kx = 0; kx < 3; kx++) {
                    float4 wv = *(const float4*)&sW[ic][ky * 3 + kx][ocq];
#pragma unroll
                    for (int j = 0; j < 8; j++) {
                        float iv = (kx == 0) ? rv[j].x
                                 : (kx == 1) ? rv[j].y
                                             : rv[j + 1].x;
                        acc[j][0] = fmaf(iv, wv.x, acc[j][0]);
                        acc[j][1] = fmaf(iv, wv.y, acc[j][1]);
                        acc[j][2] = fmaf(iv, wv.z, acc[j][2]);
                        acc[j][3] = fmaf(iv, wv.w, acc[j][3]);
                    }
                }
            }
        }
    }

#pragma unroll
    for (int j = 0; j < 8; j++)
#pragma unroll
        for (int q = 0; q < 4; q++) {
            int oc = oc0 + ocq + q;
            float v = acc[j][q] + b[oc];
            if (DO_GELU) v = gelu_tanh(v);
            out[((n * COUT + oc) * HOUT + oy0 + oy) * HOUT + ox0 + ox8 + j] = v;
        }
}

// ---------------------------------------------------------------------------
// convR4: conv4 variant — same per-thread economics as convR (4oc x 8px,
// float2 kx-reuse, 12 LDS per 96 FMA) but 128-thread CTA with a 64oc x
// (4 rows x 8 cols) tile -> grid 512 CTAs (3.5 CTAs/SM, 14 warps/SM, with
// cross-CTA load/compute overlap). Accumulation order per output unchanged.
// smem: sIn[8][9][18] + sW[8][9][64] = 23.6 KB.
// ---------------------------------------------------------------------------
template <int CIN, int COUT, int HIN, int HOUT, bool DO_GELU>
__global__ __launch_bounds__(128) void convR4_kernel(
    const float* __restrict__ in, const float* __restrict__ w,
    const float* __restrict__ b, float* __restrict__ out)
{
    __shared__ __align__(16) float sIn[8][9][18];    // 9 rows x 17 cols (+pad)
    __shared__ __align__(16) float sW[8][9][64];

    int n = blockIdx.z;
    int oc0 = blockIdx.y * 64;
    const int tiles_x = HOUT / 8;                    // 2 for HOUT=16
    int ty = blockIdx.x / tiles_x;                   // 0..HOUT/4-1 over rows of 4
    int txo = blockIdx.x % tiles_x;
    int oy0 = ty * 4, ox0 = txo * 8;
    int tid = threadIdx.x;

    int ocq = (tid & 15) * 4;                        // 16 oc groups
    int oy = tid >> 4;                               // 0..7 -> but only 4 rows:
    // 128 threads = 16 ocg x 8 rowslots; tile has 4 rows x 8 px, each thread
    // does one full row of 8 px; rowslots 4..7 handle second half? No — tile
    // is 4 rows, so use 8 rowslots = 4 rows x 2 halves? Full row = 8 px wide,
    // so: oy = (tid >> 4) & 3 (4 rows), second bit selects nothing. Instead:
    // 16 ocg x 4 rows = 64 threads... we need 128. Split oc further:
    // ocq covers 64 oc via (tid & 31) * 2? Keep it simple: 32 ocg x 4 rows.
    int ocg = tid & 31;                              // 32 groups x 2 oc
    int row = tid >> 5;                              // 0..3
    int oc2 = ocg * 2;                               // 2 oc per thread
    (void)ocq; (void)oy;

    // thread = 2 oc x 8 px  (16 outputs). Per (ic,ky): 9 float2 input LDS +
    // 3 LDS.64 weight = 12 LDS per 48 FMA. (Half convR's FMA/LDS, but CTA
    // count compensates; weights broadcast-free.)
    float acc[8][2];
#pragma unroll
    for (int j = 0; j < 8; j++) { acc[j][0] = 0.0f; acc[j][1] = 0.0f; }

    for (int ic0 = 0; ic0 < CIN; ic0 += 8) {
        __syncthreads();
        for (int idx = tid; idx < 4608; idx += 128) {
            int oc = idx / 72, r = idx % 72;
            int ic = r / 9, kk = r % 9;
            sW[ic][kk][oc] = w[(oc0 + oc) * (CIN * 9) + (ic0 + ic) * 9 + kk];
        }
        for (int idx = tid; idx < 8 * 9 * 17; idx += 128) {
            int ic = idx / 153;
            int rem = idx - ic * 153;
            int r = rem / 17, c = rem - r * 17;
            int iy = oy0 * 2 + r, ix = ox0 * 2 + c;
            float v = 0.0f;
            if (iy < HIN && ix < HIN)
                v = in[((n * CIN + ic0 + ic) * HIN + iy) * HIN + ix];
            sIn[ic][r][c] = v;
        }
        __syncthreads();

#pragma unroll
        for (int ic = 0; ic < 8; ic++) {
#pragma unroll
            for (int ky = 0; ky < 3; ky++) {
                const float* rowp = &sIn[ic][row * 2 + ky][0];
                float2 rv[9];
#pragma unroll
                for (int i = 0; i < 9; i++)
                    rv[i] = *(const float2*)(rowp + 2 * i);
#pragma unroll
                for (int kx = 0; kx < 3; kx++) {
                    float2 wv = *(const float2*)&sW[ic][ky * 3 + kx][oc2];
#pragma unroll
                    for (int j = 0; j < 8; j++) {
                        float iv = (kx == 0) ? rv[j].x
                                 : (kx == 1) ? rv[j].y
                                             : rv[j + 1].x;
                        acc[j][0] = fmaf(iv, wv.x, acc[j][0]);
                        acc[j][1] = fmaf(iv, wv.y, acc[j][1]);
                    }
                }
            }
        }
    }

#pragma unroll
    for (int j = 0; j < 8; j++)
#pragma unroll
        for (int q = 0; q < 2; q++) {
            int oc = oc0 + oc2 + q;
            float v = acc[j][q] + b[oc];
            if (DO_GELU) v = gelu_tanh(v);
            out[((n * COUT + oc) * HOUT + oy0 + row) * HOUT + ox0 + j] = v;
        }
}

// ---------------------------------------------------------------------------
// kproj: kprojT[m][c][k] = sum_d codebook[m][k][d] * wk[m][c][d]  (transposed)
// ---------------------------------------------------------------------------
__global__ __launch_bounds__(256) void kproj_kernel(
    const float* __restrict__ codebook, const float* __restrict__ wk)
{
    int idx = blockIdx.x * 256 + threadIdx.x;   // 65536 total
    int c = idx & 63;
    int k = (idx >> 6) & 255;
    int m = idx >> 14;
    const float* cb = codebook + (m * 256 + k) * 64;
    const float* wkp = wk + (m * 64 + c) * 64;
    float s = 0.0f;
#pragma unroll
    for (int d = 0; d < 64; d++) s = fmaf(cb[d], wkp[d], s);
    g_kprojT[(m * 64 + c) * 256 + k] = s;
}

// ---------------------------------------------------------------------------
// score v2: grid (pxtile=8, m=4, n=16) = 512 blocks, 256 threads.
// ---------------------------------------------------------------------------
__global__ __launch_bounds__(256) void score2_kernel(
    const float* __restrict__ wq, unsigned char* __restrict__ out_raw,
    int mode, int has_hw)
{
    __shared__ float qsT[64 * 36];      // [d][px]  (pad 36)
    __shared__ float qpT[64 * 36];      // [c][px]
    __shared__ float wqs[64 * 65];      // [c][d]   (pad 65)

    int t = threadIdx.x;
    int pt = blockIdx.x;                // 0..7 px tiles of 32
    int m = blockIdx.y;
    int n = blockIdx.z;

    for (int idx = t; idx < 64 * 32; idx += 256) {
        int d = idx >> 5, px = idx & 31;
        qsT[d * 36 + px] = g_buf4[(n * 256 + m * 64 + d) * 256 + pt * 32 + px];
    }
    for (int idx = t; idx < 4096; idx += 256) {
        int c = idx >> 6, d = idx & 63;
        wqs[c * 65 + d] = wq[(m * 64 + c) * 64 + d];
    }
    __syncthreads();

    {
        int c = t & 63, pxg = t >> 6;   // 4 groups of 8 px
        float a0 = 0, a1 = 0, a2 = 0, a3 = 0, a4 = 0, a5 = 0, a6 = 0, a7 = 0;
#pragma unroll 8
        for (int d = 0; d < 64; d++) {
            float wv = wqs[c * 65 + d];
            const float* qr = &qsT[d * 36 + pxg * 8];
            float4 qa = *(const float4*)qr;
            float4 qb = *(const float4*)(qr + 4);
            a0 = fmaf(wv, qa.x, a0); a1 = fmaf(wv, qa.y, a1);
            a2 = fmaf(wv, qa.z, a2); a3 = fmaf(wv, qa.w, a3);
            a4 = fmaf(wv, qb.x, a4); a5 = fmaf(wv, qb.y, a5);
            a6 = fmaf(wv, qb.z, a6); a7 = fmaf(wv, qb.w, a7);
        }
        float* qo = &qpT[c * 36 + pxg * 8];
        qo[0] = a0; qo[1] = a1; qo[2] = a2; qo[3] = a3;
        qo[4] = a4; qo[5] = a5; qo[6] = a6; qo[7] = a7;
    }
    __syncthreads();

    int px = t & 31, kgrp = t >> 5;     // 8 groups x 32 k
    int k0 = kgrp * 32;
    float acc[32];
#pragma unroll
    for (int k = 0; k < 32; k++) acc[k] = 0.0f;

    const float* kbase = g_kprojT + (m * 64) * 256 + k0;
    for (int c = 0; c < 64; c++) {
        float qv = qpT[c * 36 + px];
        const float4* kr = (const float4*)(kbase + c * 256);
#pragma unroll
        for (int v = 0; v < 8; v++) {
            float4 kv = __ldg(kr + v);
            acc[v * 4 + 0] = fmaf(qv, kv.x, acc[v * 4 + 0]);
            acc[v * 4 + 1] = fmaf(qv, kv.y, acc[v * 4 + 1]);
            acc[v * 4 + 2] = fmaf(qv, kv.z, acc[v * 4 + 2]);
            acc[v * 4 + 3] = fmaf(qv, kv.w, acc[v * 4 + 3]);
        }
    }

    float best = -3.402823466e38f;
    int bi = 0;
#pragma unroll
    for (int k = 0; k < 32; k++)
        if (acc[k] > best) { best = acc[k]; bi = k0 + k; }  // strict > = first max

    __syncthreads();
    float* redV = qsT;
    int* redI = (int*)(qsT + 256);
    redV[t] = best;
    redI[t] = bi;
    __syncthreads();

    if (t < 32) {
        float bv = redV[t];
        int bx = redI[t];
#pragma unroll
        for (int g = 1; g < 8; g++) {
            float v = redV[g * 32 + t];
            int i2 = redI[g * 32 + t];
            if (v > bv || (v == bv && i2 < bx)) { bv = v; bx = i2; }
        }
        int oidx = (n * 256 + pt * 32 + t) * 4 + m;
        if (mode == 0)      ((unsigned char*)out_raw)[oidx] = (unsigned char)bx;
        else if (mode == 1) ((int*)out_raw)[oidx] = bx;
        else                ((float*)out_raw)[oidx] = (float)bx;
    }
    if (blockIdx.x == 0 && blockIdx.y == 0 && blockIdx.z == 0 && t == 0 && has_hw) {
        if (mode == 0) {
            int* hw = (int*)(out_raw + 16384);
            hw[0] = 256; hw[1] = 256;
        } else if (mode == 1) {
            int* hw = (int*)out_raw;
            hw[16384] = 256; hw[16385] = 256;
        } else {
            float* hw = (float*)out_raw;
            hw[16384] = 256.0f; hw[16385] = 256.0f;
        }
    }
}

// ---------------------------------------------------------------------------
// launch
// ---------------------------------------------------------------------------
extern "C" void kernel_launch(void* const* d_in, const int* in_sizes, int n_in,
                              void* d_out, int out_size)
{
    // defensive input remap by element count
    int ix = 0, iw1 = 1, ib1 = 2, iw2 = 3, ib2 = 4, iw3 = 5, ib3 = 6,
        iw4 = 7, ib4 = 8, icb = 9, iwq = 10, iwk = 11;
    if (n_in == 12) {
        int p256[2] = {-1, -1}, np256 = 0;
        int p16k[2] = {-1, -1}, np16k = 0;
        int xpos = -1;
        for (int i = 0; i < 12; i++) {
            switch (in_sizes[i]) {
                case 3145728: ix = i; xpos = i; break;
                case 1728:    iw1 = i; break;
                case 64:      ib1 = i; break;
                case 73728:   iw2 = i; break;
                case 128:     ib2 = i; break;
                case 294912:  iw3 = i; break;
                case 589824:  iw4 = i; break;
                case 65536:   icb = i; break;
                case 256:     if (np256 < 2) p256[np256++] = i; break;
                case 16384:   if (np16k < 2) p16k[np16k++] = i; break;
                default: break;
            }
        }
        if (np256 == 2) { ib3 = p256[0]; ib4 = p256[1]; }
        if (np16k == 2) {
            if (xpos >= 0 && xpos < p16k[0]) { iwq = p16k[0]; iwk = p16k[1]; }
            else                             { iwk = p16k[0]; iwq = p16k[1]; }
        }
    }

    const float* x        = (const float*)d_in[ix];
    const float* w1       = (const float*)d_in[iw1];
    const float* b1       = (const float*)d_in[ib1];
    const float* w2       = (const float*)d_in[iw2];
    const float* b2       = (const float*)d_in[ib2];
    const float* w3       = (const float*)d_in[iw3];
    const float* b3       = (const float*)d_in[ib3];
    const float* w4       = (const float*)d_in[iw4];
    const float* b4       = (const float*)d_in[ib4];
    const float* codebook = (const float*)d_in[icb];
    const float* wq       = (const float*)d_in[iwq];
    const float* wk       = (const float*)d_in[iwk];

    float *buf1, *buf2, *buf3, *buf4;
    cudaGetSymbolAddress((void**)&buf1, g_buf1);
    cudaGetSymbolAddress((void**)&buf2, g_buf2);
    cudaGetSymbolAddress((void**)&buf3, g_buf3);
    cudaGetSymbolAddress((void**)&buf4, g_buf4);

    // conv1: 256 tiles x 16 images
    conv1_kernel<<<dim3(256, 1, NIMG), 256>>>(x, w1, b1);
    // conv2: 64->128, 128->64; convR tiles (64/8)*(64/16)=32 x 2 ocb
    convR_kernel<64, 128, 128, 64, true>
        <<<dim3(32, 2, NIMG), 256>>>(buf1, w2, b2, buf2);
    // conv3: 128->256, 64->32; convR tiles (32/8)*(32/16)=8 x 4 ocb
    convR_kernel<128, 256, 64, 32, true>
        <<<dim3(8, 4, NIMG), 256>>>(buf2, w3, b3, buf3);
    // conv4: 256->256, 32->16; convR4, tiles (16/4)*(16/8)=8 x 4 ocb -> 512 CTAs
    convR4_kernel<256, 256, 32, 16, false>
        <<<dim3(8, 4, NIMG), 128>>>(buf3, w4, b4, buf4);
    // kproj (transposed output)
    kproj_kernel<<<256, 256>>>(codebook, wk);

    int mode, has_hw;
    if (out_size == 16386)      { mode = 2; has_hw = 1; }
    else if (out_size >= 16392) { mode = 0; has_hw = 1; }
    else                        { mode = 0; has_hw = 0; }

    score2_kernel<<<dim3(8, 4, NIMG), 256>>>(wq, (unsigned char*)d_out,
                                             mode, has_hw);
}

// round 13
// speedup vs baseline: 1.0775x; 1.0775x over previous
#include <cuda_runtime.h>
#include <math.h>

// ---------------------------------------------------------------------------
// RefEncoder: 4x stride-2 3x3 convs (SAME pad = 0 before / 1 after), gelu(tanh)
// on first three, then per-group query proj + codebook-key proj + argmax.
// ---------------------------------------------------------------------------

#define NIMG 16

__device__ float g_buf1[NIMG * 64 * 128 * 128];   // conv1 out (gelu)
__device__ float g_buf2[NIMG * 128 * 64 * 64];    // conv2 out (gelu)
__device__ float g_buf3[NIMG * 256 * 32 * 32];    // conv3 out (gelu)
__device__ float g_buf4[NIMG * 256 * 16 * 16];    // conv4 out (latent)
__device__ float g_kprojT[4 * 64 * 256];          // kproj transposed [m][c][k]

__device__ __forceinline__ float gelu_tanh(float x) {
    float x3 = x * x * x;
    float t = tanhf(0.7978845608028654f * (x + 0.044715f * x3));
    return 0.5f * x * (1.0f + t);
}

// ---------------------------------------------------------------------------
// conv1: Cin=3, Cout=64, 256 -> 128, normalize input (2x-1), gelu output.
// Swapped warp mapping: warp = 2 oc-groups x 16 sp slots -> weight LDS.128
// broadcasts (1 wf); sIn row pad 19 makes the 16 input scalars conflict-free.
// ---------------------------------------------------------------------------
__global__ __launch_bounds__(256) void conv1_kernel(
    const float* __restrict__ x, const float* __restrict__ w,
    const float* __restrict__ b)
{
    const int HIN = 256, HOUT = 128;
    __shared__ float sIn[3][17][19];
    __shared__ __align__(16) float sW[3][9][64];

    int n = blockIdx.z;
    int tiles_x = HOUT / 8;
    int ty = blockIdx.x / tiles_x;
    int txo = blockIdx.x % tiles_x;
    int oy0 = ty * 8, ox0 = txo * 8;
    int tid = threadIdx.x;

    for (int idx = tid; idx < 1728; idx += 256) {
        int oc = idx / 27, r = idx % 27;
        int ic = r / 9, kk = r % 9;
        sW[ic][kk][oc] = w[idx];
    }
    for (int idx = tid; idx < 3 * 17 * 17; idx += 256) {
        int ic = idx / 289, r2 = idx % 289;
        int r = r2 / 17, c = r2 % 17;
        int iy = oy0 * 2 + r, ix = ox0 * 2 + c;
        float v = 0.0f;
        if (iy < HIN && ix < HIN)
            v = 2.0f * x[((n * 3 + ic) * HIN + iy) * HIN + ix] - 1.0f;
        sIn[ic][r][c] = v;
    }
    __syncthreads();

    int ocq = (tid >> 4) * 4;           // swapped: warp = 2 ocg x 16 sp
    int sp = (tid & 15) * 4;
    int oy = sp >> 3, oxl = sp & 7;

    float acc[4][4];
#pragma unroll
    for (int j = 0; j < 4; j++)
#pragma unroll
        for (int q = 0; q < 4; q++) acc[j][q] = 0.0f;

#pragma unroll
    for (int ic = 0; ic < 3; ic++) {
#pragma unroll
        for (int kk = 0; kk < 9; kk++) {
            float4 wv = *(const float4*)&sW[ic][kk][ocq];
#pragma unroll
            for (int j = 0; j < 4; j++) {
                float iv = sIn[ic][oy * 2 + kk / 3][(oxl + j) * 2 + kk % 3];
                acc[j][0] = fmaf(iv, wv.x, acc[j][0]);
                acc[j][1] = fmaf(iv, wv.y, acc[j][1]);
                acc[j][2] = fmaf(iv, wv.z, acc[j][2]);
                acc[j][3] = fmaf(iv, wv.w, acc[j][3]);
            }
        }
    }
#pragma unroll
    for (int j = 0; j < 4; j++)
#pragma unroll
        for (int q = 0; q < 4; q++) {
            int oc = ocq + q;
            float v = acc[j][q] + b[oc];
            g_buf1[((n * 64 + oc) * HOUT + oy0 + oy) * HOUT + ox0 + oxl + j] =
                gelu_tanh(v);
        }
}

// ---------------------------------------------------------------------------
// convR: register-blocked stride-2 3x3 conv (R6's best; conv2/conv3).
// CTA: 256 threads, tile = 64 oc x (8 rows x 16 cols). Thread: 4 oc x 8 px,
// float2 reuse across kx (kk = ky*3+kx ascending -> bit-identical order).
// Mapping kept as-is: inputs broadcast; swap would bank-conflict float2 rows.
// ---------------------------------------------------------------------------
template <int CIN, int COUT, int HIN, int HOUT, bool DO_GELU>
__global__ __launch_bounds__(256) void convR_kernel(
    const float* __restrict__ in, const float* __restrict__ w,
    const float* __restrict__ b, float* __restrict__ out)
{
    __shared__ __align__(16) float sIn[8][17][34];   // 33 cols used (+1 pad)
    __shared__ __align__(16) float sW[8][9][64];

    int n = blockIdx.z;
    int oc0 = blockIdx.y * 64;
    const int tiles_x = HOUT / 16;
    int ty = (tiles_x > 1) ? ((int)blockIdx.x / tiles_x) : (int)blockIdx.x;
    int txo = (tiles_x > 1) ? ((int)blockIdx.x % tiles_x) : 0;
    int oy0 = ty * 8, ox0 = txo * 16;
    int tid = threadIdx.x;

    int ocq = (tid & 15) * 4;
    int sp = tid >> 4;                               // 0..15
    int oy = sp >> 1;                                // 0..7
    int ox8 = (sp & 1) * 8;                          // 0 or 8

    float acc[8][4];
#pragma unroll
    for (int j = 0; j < 8; j++)
#pragma unroll
        for (int q = 0; q < 4; q++) acc[j][q] = 0.0f;

    for (int ic0 = 0; ic0 < CIN; ic0 += 8) {
        __syncthreads();
        for (int idx = tid; idx < 4608; idx += 256) {
            int oc = idx / 72, r = idx % 72;
            int ic = r / 9, kk = r % 9;
            sW[ic][kk][oc] = w[(oc0 + oc) * (CIN * 9) + (ic0 + ic) * 9 + kk];
        }
        for (int idx = tid; idx < 8 * 17 * 33; idx += 256) {
            int ic = idx / 561;
            int rem = idx - ic * 561;
            int r = rem / 33, c = rem - r * 33;
            int iy = oy0 * 2 + r, ix = ox0 * 2 + c;
            float v = 0.0f;
            if (iy < HIN && ix < HIN)
                v = in[((n * CIN + ic0 + ic) * HIN + iy) * HIN + ix];
            sIn[ic][r][c] = v;
        }
        __syncthreads();

#pragma unroll
        for (int ic = 0; ic < 8; ic++) {
#pragma unroll
            for (int ky = 0; ky < 3; ky++) {
                const float* row = &sIn[ic][oy * 2 + ky][2 * ox8];
                float2 rv[9];
#pragma unroll
                for (int i = 0; i < 9; i++)
                    rv[i] = *(const float2*)(row + 2 * i);
#pragma unroll
                for (int kx = 0; kx < 3; kx++) {
                    float4 wv = *(const float4*)&sW[ic][ky * 3 + kx][ocq];
#pragma unroll
                    for (int j = 0; j < 8; j++) {
                        float iv = (kx == 0) ? rv[j].x
                                 : (kx == 1) ? rv[j].y
                                             : rv[j + 1].x;
                        acc[j][0] = fmaf(iv, wv.x, acc[j][0]);
                        acc[j][1] = fmaf(iv, wv.y, acc[j][1]);
                        acc[j][2] = fmaf(iv, wv.z, acc[j][2]);
                        acc[j][3] = fmaf(iv, wv.w, acc[j][3]);
                    }
                }
            }
        }
    }

#pragma unroll
    for (int j = 0; j < 8; j++)
#pragma unroll
        for (int q = 0; q < 4; q++) {
            int oc = oc0 + ocq + q;
            float v = acc[j][q] + b[oc];
            if (DO_GELU) v = gelu_tanh(v);
            out[((n * COUT + oc) * HOUT + oy0 + oy) * HOUT + ox0 + ox8 + j] = v;
        }
}

// ---------------------------------------------------------------------------
// convV1S: v1 conv (4oc x 4px, 8x8 tile, 256 thr) with SWAPPED warp mapping
// and pad-19 sIn rows. Weight LDS.128 becomes a 2-address broadcast (1 wf,
// was 2); the 16 distinct input scalars land on disjoint banks (pad 19 =>
// bank = 6*oy + 8*half + const, sets provably disjoint). 6 -> 5 wavefronts
// per (ic,kk) per warp. Per-output fmaf order identical to v1. Used: conv4.
// ---------------------------------------------------------------------------
template <int CIN, int COUT, int HIN, int HOUT, bool DO_GELU>
__global__ __launch_bounds__(256) void convV1S_kernel(
    const float* __restrict__ in, const float* __restrict__ w,
    const float* __restrict__ b, float* __restrict__ out)
{
    __shared__ float sIn[8][17][19];
    __shared__ __align__(16) float sW[8][9][64];

    int n = blockIdx.z;
    int oc0 = blockIdx.y * 64;
    const int tiles_x = HOUT / 8;
    int ty = blockIdx.x / tiles_x;
    int txo = blockIdx.x % tiles_x;
    int oy0 = ty * 8, ox0 = txo * 8;
    int tid = threadIdx.x;

    int ocq = (tid >> 4) * 4;           // swapped: warp = 2 ocg x 16 sp
    int sp = (tid & 15) * 4;
    int oy = sp >> 3, oxl = sp & 7;

    float acc[4][4];
#pragma unroll
    for (int j = 0; j < 4; j++)
#pragma unroll
        for (int q = 0; q < 4; q++) acc[j][q] = 0.0f;

    for (int ic0 = 0; ic0 < CIN; ic0 += 8) {
        __syncthreads();
        for (int idx = tid; idx < 4608; idx += 256) {
            int oc = idx / 72, r = idx % 72;
            int ic = r / 9, kk = r % 9;
            sW[ic][kk][oc] = w[(oc0 + oc) * (CIN * 9) + (ic0 + ic) * 9 + kk];
        }
        for (int idx = tid; idx < 2312; idx += 256) {
            int ic = idx / 289, r2 = idx % 289;
            int r = r2 / 17, c = r2 % 17;
            int iy = oy0 * 2 + r, ix = ox0 * 2 + c;
            float v = 0.0f;
            if (iy < HIN && ix < HIN)
                v = in[((n * CIN + ic0 + ic) * HIN + iy) * HIN + ix];
            sIn[ic][r][c] = v;
        }
        __syncthreads();

#pragma unroll
        for (int ic = 0; ic < 8; ic++) {
#pragma unroll
            for (int kk = 0; kk < 9; kk++) {
                float4 wv = *(const float4*)&sW[ic][kk][ocq];
#pragma unroll
                for (int j = 0; j < 4; j++) {
                    float iv = sIn[ic][oy * 2 + kk / 3][(oxl + j) * 2 + kk % 3];
                    acc[j][0] = fmaf(iv, wv.x, acc[j][0]);
                    acc[j][1] = fmaf(iv, wv.y, acc[j][1]);
                    acc[j][2] = fmaf(iv, wv.z, acc[j][2]);
                    acc[j][3] = fmaf(iv, wv.w, acc[j][3]);
                }
            }
        }
    }

#pragma unroll
    for (int j = 0; j < 4; j++)
#pragma unroll
        for (int q = 0; q < 4; q++) {
            int oc = oc0 + ocq + q;
            float v = acc[j][q] + b[oc];
            if (DO_GELU) v = gelu_tanh(v);
            out[((n * COUT + oc) * HOUT + oy0 + oy) * HOUT + ox0 + oxl + j] = v;
        }
}

// ---------------------------------------------------------------------------
// kproj: kprojT[m][c][k] = sum_d codebook[m][k][d] * wk[m][c][d]  (transposed)
// ---------------------------------------------------------------------------
__global__ __launch_bounds__(256) void kproj_kernel(
    const float* __restrict__ codebook, const float* __restrict__ wk)
{
    int idx = blockIdx.x * 256 + threadIdx.x;   // 65536 total
    int c = idx & 63;
    int k = (idx >> 6) & 255;
    int m = idx >> 14;
    const float* cb = codebook + (m * 256 + k) * 64;
    const float* wkp = wk + (m * 64 + c) * 64;
    float s = 0.0f;
#pragma unroll
    for (int d = 0; d < 64; d++) s = fmaf(cb[d], wkp[d], s);
    g_kprojT[(m * 64 + c) * 256 + k] = s;
}

// ---------------------------------------------------------------------------
// score v2: grid (pxtile=8, m=4, n=16) = 512 blocks, 256 threads.
// ---------------------------------------------------------------------------
__global__ __launch_bounds__(256) void score2_kernel(
    const float* __restrict__ wq, unsigned char* __restrict__ out_raw,
    int mode, int has_hw)
{
    __shared__ float qsT[64 * 36];      // [d][px]  (pad 36)
    __shared__ float qpT[64 * 36];      // [c][px]
    __shared__ float wqs[64 * 65];      // [c][d]   (pad 65)

    int t = threadIdx.x;
    int pt = blockIdx.x;                // 0..7 px tiles of 32
    int m = blockIdx.y;
    int n = blockIdx.z;

    for (int idx = t; idx < 64 * 32; idx += 256) {
        int d = idx >> 5, px = idx & 31;
        qsT[d * 36 + px] = g_buf4[(n * 256 + m * 64 + d) * 256 + pt * 32 + px];
    }
    for (int idx = t; idx < 4096; idx += 256) {
        int c = idx >> 6, d = idx & 63;
        wqs[c * 65 + d] = wq[(m * 64 + c) * 64 + d];
    }
    __syncthreads();

    {
        int c = t & 63, pxg = t >> 6;   // 4 groups of 8 px
        float a0 = 0, a1 = 0, a2 = 0, a3 = 0, a4 = 0, a5 = 0, a6 = 0, a7 = 0;
#pragma unroll 8
        for (int d = 0; d < 64; d++) {
            float wv = wqs[c * 65 + d];
            const float* qr = &qsT[d * 36 + pxg * 8];
            float4 qa = *(const float4*)qr;
            float4 qb = *(const float4*)(qr + 4);
            a0 = fmaf(wv, qa.x, a0); a1 = fmaf(wv, qa.y, a1);
            a2 = fmaf(wv, qa.z, a2); a3 = fmaf(wv, qa.w, a3);
            a4 = fmaf(wv, qb.x, a4); a5 = fmaf(wv, qb.y, a5);
            a6 = fmaf(wv, qb.z, a6); a7 = fmaf(wv, qb.w, a7);
        }
        float* qo = &qpT[c * 36 + pxg * 8];
        qo[0] = a0; qo[1] = a1; qo[2] = a2; qo[3] = a3;
        qo[4] = a4; qo[5] = a5; qo[6] = a6; qo[7] = a7;
    }
    __syncthreads();

    int px = t & 31, kgrp = t >> 5;     // 8 groups x 32 k
    int k0 = kgrp * 32;
    float acc[32];
#pragma unroll
    for (int k = 0; k < 32; k++) acc[k] = 0.0f;

    const float* kbase = g_kprojT + (m * 64) * 256 + k0;
    for (int c = 0; c < 64; c++) {
        float qv = qpT[c * 36 + px];
        const float4* kr = (const float4*)(kbase + c * 256);
#pragma unroll
        for (int v = 0; v < 8; v++) {
            float4 kv = __ldg(kr + v);
            acc[v * 4 + 0] = fmaf(qv, kv.x, acc[v * 4 + 0]);
            acc[v * 4 + 1] = fmaf(qv, kv.y, acc[v * 4 + 1]);
            acc[v * 4 + 2] = fmaf(qv, kv.z, acc[v * 4 + 2]);
            acc[v * 4 + 3] = fmaf(qv, kv.w, acc[v * 4 + 3]);
        }
    }

    float best = -3.402823466e38f;
    int bi = 0;
#pragma unroll
    for (int k = 0; k < 32; k++)
        if (acc[k] > best) { best = acc[k]; bi = k0 + k; }  // strict > = first max

    __syncthreads();
    float* redV = qsT;
    int* redI = (int*)(qsT + 256);
    redV[t] = best;
    redI[t] = bi;
    __syncthreads();

    if (t < 32) {
        float bv = redV[t];
        int bx = redI[t];
#pragma unroll
        for (int g = 1; g < 8; g++) {
            float v = redV[g * 32 + t];
            int i2 = redI[g * 32 + t];
            if (v > bv || (v == bv && i2 < bx)) { bv = v; bx = i2; }
        }
        int oidx = (n * 256 + pt * 32 + t) * 4 + m;
        if (mode == 0)      ((unsigned char*)out_raw)[oidx] = (unsigned char)bx;
        else if (mode == 1) ((int*)out_raw)[oidx] = bx;
        else                ((float*)out_raw)[oidx] = (float)bx;
    }
    if (blockIdx.x == 0 && blockIdx.y == 0 && blockIdx.z == 0 && t == 0 && has_hw) {
        if (mode == 0) {
            int* hw = (int*)(out_raw + 16384);
            hw[0] = 256; hw[1] = 256;
        } else if (mode == 1) {
            int* hw = (int*)out_raw;
            hw[16384] = 256; hw[16385] = 256;
        } else {
            float* hw = (float*)out_raw;
            hw[16384] = 256.0f; hw[16385] = 256.0f;
        }
    }
}

// ---------------------------------------------------------------------------
// launch
// ---------------------------------------------------------------------------
extern "C" void kernel_launch(void* const* d_in, const int* in_sizes, int n_in,
                              void* d_out, int out_size)
{
    // defensive input remap by element count
    int ix = 0, iw1 = 1, ib1 = 2, iw2 = 3, ib2 = 4, iw3 = 5, ib3 = 6,
        iw4 = 7, ib4 = 8, icb = 9, iwq = 10, iwk = 11;
    if (n_in == 12) {
        int p256[2] = {-1, -1}, np256 = 0;
        int p16k[2] = {-1, -1}, np16k = 0;
        int xpos = -1;
        for (int i = 0; i < 12; i++) {
            switch (in_sizes[i]) {
                case 3145728: ix = i; xpos = i; break;
                case 1728:    iw1 = i; break;
                case 64:      ib1 = i; break;
                case 73728:   iw2 = i; break;
                case 128:     ib2 = i; break;
                case 294912:  iw3 = i; break;
                case 589824:  iw4 = i; break;
                case 65536:   icb = i; break;
                case 256:     if (np256 < 2) p256[np256++] = i; break;
                case 16384:   if (np16k < 2) p16k[np16k++] = i; break;
                default: break;
            }
        }
        if (np256 == 2) { ib3 = p256[0]; ib4 = p256[1]; }
        if (np16k == 2) {
            if (xpos >= 0 && xpos < p16k[0]) { iwq = p16k[0]; iwk = p16k[1]; }
            else                             { iwk = p16k[0]; iwq = p16k[1]; }
        }
    }

    const float* x        = (const float*)d_in[ix];
    const float* w1       = (const float*)d_in[iw1];
    const float* b1       = (const float*)d_in[ib1];
    const float* w2       = (const float*)d_in[iw2];
    const float* b2       = (const float*)d_in[ib2];
    const float* w3       = (const float*)d_in[iw3];
    const float* b3       = (const float*)d_in[ib3];
    const float* w4       = (const float*)d_in[iw4];
    const float* b4       = (const float*)d_in[ib4];
    const float* codebook = (const float*)d_in[icb];
    const float* wq       = (const float*)d_in[iwq];
    const float* wk       = (const float*)d_in[iwk];

    float *buf1, *buf2, *buf3, *buf4;
    cudaGetSymbolAddress((void**)&buf1, g_buf1);
    cudaGetSymbolAddress((void**)&buf2, g_buf2);
    cudaGetSymbolAddress((void**)&buf3, g_buf3);
    cudaGetSymbolAddress((void**)&buf4, g_buf4);

    // conv1: 256 tiles x 16 images (swapped mapping)
    conv1_kernel<<<dim3(256, 1, NIMG), 256>>>(x, w1, b1);
    // conv2: 64->128, 128->64; convR tiles (64/8)*(64/16)=32 x 2 ocb
    convR_kernel<64, 128, 128, 64, true>
        <<<dim3(32, 2, NIMG), 256>>>(buf1, w2, b2, buf2);
    // conv3: 128->256, 64->32; convR tiles (32/8)*(32/16)=8 x 4 ocb
    convR_kernel<128, 256, 64, 32, true>
        <<<dim3(8, 4, NIMG), 256>>>(buf2, w3, b3, buf3);
    // conv4: 256->256, 32->16; swapped v1, tiles 4 x 4 ocb -> 256 CTAs
    convV1S_kernel<256, 256, 32, 16, false>
        <<<dim3(4, 4, NIMG), 256>>>(buf3, w4, b4, buf4);
    // kproj (transposed output)
    kproj_kernel<<<256, 256>>>(codebook, wk);

    int mode, has_hw;
    if (out_size == 16386)      { mode = 2; has_hw = 1; }
    else if (out_size >= 16392) { mode = 0; has_hw = 1; }
    else                        { mode = 0; has_hw = 0; }

    score2_kernel<<<dim3(8, 4, NIMG), 256>>>(wq, (unsigned char*)d_out,
                                             mode, has_hw);
}

// round 17
// speedup vs baseline: 1.0922x; 1.0136x over previous
#include <cuda_runtime.h>
#include <math.h>

// ---------------------------------------------------------------------------
// RefEncoder: 4x stride-2 3x3 convs (SAME pad = 0 before / 1 after), gelu(tanh)
// on first three, then per-group query proj + codebook-key proj + argmax.
// ---------------------------------------------------------------------------

#define NIMG 16

__device__ float g_buf1[NIMG * 64 * 128 * 128];   // conv1 out (gelu)
__device__ float g_buf2[NIMG * 128 * 64 * 64];    // conv2 out (gelu)
__device__ float g_buf3[NIMG * 256 * 32 * 32];    // conv3 out (gelu)
__device__ float g_buf4[NIMG * 256 * 16 * 16];    // conv4 out (latent)
__device__ float g_kprojT[4 * 64 * 256];          // kproj transposed [m][c][k]

__device__ __forceinline__ float gelu_tanh(float x) {
    float x3 = x * x * x;
    float t = tanhf(0.7978845608028654f * (x + 0.044715f * x3));
    return 0.5f * x * (1.0f + t);
}

// ---------------------------------------------------------------------------
// conv1: Cin=3, Cout=64, 256 -> 128, normalize input (2x-1), gelu output.
// (R6 original mapping — best measured.)
// ---------------------------------------------------------------------------
__global__ __launch_bounds__(256) void conv1_kernel(
    const float* __restrict__ x, const float* __restrict__ w,
    const float* __restrict__ b)
{
    const int HIN = 256, HOUT = 128;
    __shared__ float sIn[3][17][18];
    __shared__ __align__(16) float sW[3][9][64];

    int n = blockIdx.z;
    int tiles_x = HOUT / 8;
    int ty = blockIdx.x / tiles_x;
    int txo = blockIdx.x % tiles_x;
    int oy0 = ty * 8, ox0 = txo * 8;
    int tid = threadIdx.x;

    for (int idx = tid; idx < 1728; idx += 256) {
        int oc = idx / 27, r = idx % 27;
        int ic = r / 9, kk = r % 9;
        sW[ic][kk][oc] = w[idx];
    }
    for (int idx = tid; idx < 3 * 17 * 17; idx += 256) {
        int ic = idx / 289, r2 = idx % 289;
        int r = r2 / 17, c = r2 % 17;
        int iy = oy0 * 2 + r, ix = ox0 * 2 + c;
        float v = 0.0f;
        if (iy < HIN && ix < HIN)
            v = 2.0f * x[((n * 3 + ic) * HIN + iy) * HIN + ix] - 1.0f;
        sIn[ic][r][c] = v;
    }
    __syncthreads();

    int ocq = (tid & 15) * 4;
    int sp = (tid >> 4) * 4;
    int oy = sp >> 3, oxl = sp & 7;

    float acc[4][4];
#pragma unroll
    for (int j = 0; j < 4; j++)
#pragma unroll
        for (int q = 0; q < 4; q++) acc[j][q] = 0.0f;

#pragma unroll
    for (int ic = 0; ic < 3; ic++) {
#pragma unroll
        for (int kk = 0; kk < 9; kk++) {
            float4 wv = *(const float4*)&sW[ic][kk][ocq];
#pragma unroll
            for (int j = 0; j < 4; j++) {
                float iv = sIn[ic][oy * 2 + kk / 3][(oxl + j) * 2 + kk % 3];
                acc[j][0] = fmaf(iv, wv.x, acc[j][0]);
                acc[j][1] = fmaf(iv, wv.y, acc[j][1]);
                acc[j][2] = fmaf(iv, wv.z, acc[j][2]);
                acc[j][3] = fmaf(iv, wv.w, acc[j][3]);
            }
        }
    }
#pragma unroll
    for (int j = 0; j < 4; j++)
#pragma unroll
        for (int q = 0; q < 4; q++) {
            int oc = ocq + q;
            float v = acc[j][q] + b[oc];
            g_buf1[((n * 64 + oc) * HOUT + oy0 + oy) * HOUT + ox0 + oxl + j] =
                gelu_tanh(v);
        }
}

// ---------------------------------------------------------------------------
// convR16: convR (R6 economics: 4oc x 8px, float2 kx-reuse) with ic-chunk 16.
// Occupancy is register-bound at 2 CTAs/SM either way, so the bigger chunk
// halves barrier count / latency-exposed load phases for free.
// Chunks merge adjacent ic ranges -> global accumulation order (ic ascending,
// kk ascending per output) is bit-identical to the chunk-8 version.
// Dynamic smem: sIn[16][17][34] + sW[16][9][64] = 73856 B.
// ---------------------------------------------------------------------------
template <int CIN, int COUT, int HIN, int HOUT, bool DO_GELU>
__global__ __launch_bounds__(256) void convR16_kernel(
    const float* __restrict__ in, const float* __restrict__ w,
    const float* __restrict__ b, float* __restrict__ out)
{
    constexpr int CH = 16;
    constexpr int SIN_SZ = CH * 17 * 34;
    extern __shared__ __align__(16) float smem[];
    float* sIn = smem;                              // [CH][17][34]
    float* sW = smem + SIN_SZ;                      // [CH][9][64]

    int n = blockIdx.z;
    int oc0 = blockIdx.y * 64;
    const int tiles_x = HOUT / 16;
    int ty = (tiles_x > 1) ? ((int)blockIdx.x / tiles_x) : (int)blockIdx.x;
    int txo = (tiles_x > 1) ? ((int)blockIdx.x % tiles_x) : 0;
    int oy0 = ty * 8, ox0 = txo * 16;
    int tid = threadIdx.x;

    int ocq = (tid & 15) * 4;
    int sp = tid >> 4;                               // 0..15
    int oy = sp >> 1;                                // 0..7
    int ox8 = (sp & 1) * 8;                          // 0 or 8

    float acc[8][4];
#pragma unroll
    for (int j = 0; j < 8; j++)
#pragma unroll
        for (int q = 0; q < 4; q++) acc[j][q] = 0.0f;

    for (int ic0 = 0; ic0 < CIN; ic0 += CH) {
        __syncthreads();
        // weights chunk: 64 oc * 16 ic * 9 = 9216, [ic][kk][oc]
        for (int idx = tid; idx < 64 * CH * 9; idx += 256) {
            int oc = idx / (CH * 9), r = idx % (CH * 9);
            int ic = r / 9, kk = r % 9;
            sW[(ic * 9 + kk) * 64 + oc] =
                w[(oc0 + oc) * (CIN * 9) + (ic0 + ic) * 9 + kk];
        }
        // input patch chunk: 16 ic x 17 rows x 33 cols
        for (int idx = tid; idx < CH * 17 * 33; idx += 256) {
            int ic = idx / 561;
            int rem = idx - ic * 561;
            int r = rem / 33, c = rem - r * 33;
            int iy = oy0 * 2 + r, ix = ox0 * 2 + c;
            float v = 0.0f;
            if (iy < HIN && ix < HIN)
                v = in[((n * CIN + ic0 + ic) * HIN + iy) * HIN + ix];
            sIn[(ic * 17 + r) * 34 + c] = v;
        }
        __syncthreads();

#pragma unroll
        for (int ic = 0; ic < CH; ic++) {
#pragma unroll
            for (int ky = 0; ky < 3; ky++) {
                const float* row = &sIn[(ic * 17 + oy * 2 + ky) * 34 + 2 * ox8];
                float2 rv[9];
#pragma unroll
                for (int i = 0; i < 9; i++)
                    rv[i] = *(const float2*)(row + 2 * i);
#pragma unroll
                for (int kx = 0; kx < 3; kx++) {
                    float4 wv = *(const float4*)&sW[(ic * 9 + ky * 3 + kx) * 64 + ocq];
#pragma unroll
                    for (int j = 0; j < 8; j++) {
                        float iv = (kx == 0) ? rv[j].x
                                 : (kx == 1) ? rv[j].y
                                             : rv[j + 1].x;
                        acc[j][0] = fmaf(iv, wv.x, acc[j][0]);
                        acc[j][1] = fmaf(iv, wv.y, acc[j][1]);
                        acc[j][2] = fmaf(iv, wv.z, acc[j][2]);
                        acc[j][3] = fmaf(iv, wv.w, acc[j][3]);
                    }
                }
            }
        }
    }

#pragma unroll
    for (int j = 0; j < 8; j++)
#pragma unroll
        for (int q = 0; q < 4; q++) {
            int oc = oc0 + ocq + q;
            float v = acc[j][q] + b[oc];
            if (DO_GELU) v = gelu_tanh(v);
            out[((n * COUT + oc) * HOUT + oy0 + oy) * HOUT + ox0 + ox8 + j] = v;
        }
}

// ---------------------------------------------------------------------------
// conv v1 (4oc x 4px, 8x8 tile, 256 thr): conv4 — empirical fp32 floor
// (273 us, grid 256; reproduced 3x; all repartitions were slower).
// ---------------------------------------------------------------------------
template <int CIN, int COUT, int HIN, int HOUT, bool DO_GELU>
__global__ __launch_bounds__(256) void conv_kernel(
    const float* __restrict__ in, const float* __restrict__ w,
    const float* __restrict__ b, float* __restrict__ out)
{
    __shared__ float sIn[8][17][18];
    __shared__ __align__(16) float sW[8][9][64];

    int n = blockIdx.z;
    int oc0 = blockIdx.y * 64;
    const int tiles_x = HOUT / 8;
    int ty = blockIdx.x / tiles_x;
    int txo = blockIdx.x % tiles_x;
    int oy0 = ty * 8, ox0 = txo * 8;
    int tid = threadIdx.x;

    int ocq = (tid & 15) * 4;
    int sp = (tid >> 4) * 4;
    int oy = sp >> 3, oxl = sp & 7;

    float acc[4][4];
#pragma unroll
    for (int j = 0; j < 4; j++)
#pragma unroll
        for (int q = 0; q < 4; q++) acc[j][q] = 0.0f;

    for (int ic0 = 0; ic0 < CIN; ic0 += 8) {
        __syncthreads();
        for (int idx = tid; idx < 4608; idx += 256) {
            int oc = idx / 72, r = idx % 72;
            int ic = r / 9, kk = r % 9;
            sW[ic][kk][oc] = w[(oc0 + oc) * (CIN * 9) + (ic0 + ic) * 9 + kk];
        }
        for (int idx = tid; idx < 2312; idx += 256) {
            int ic = idx / 289, r2 = idx % 289;
            int r = r2 / 17, c = r2 % 17;
            int iy = oy0 * 2 + r, ix = ox0 * 2 + c;
            float v = 0.0f;
            if (iy < HIN && ix < HIN)
                v = in[((n * CIN + ic0 + ic) * HIN + iy) * HIN + ix];
            sIn[ic][r][c] = v;
        }
        __syncthreads();

#pragma unroll
        for (int ic = 0; ic < 8; ic++) {
#pragma unroll
            for (int kk = 0; kk < 9; kk++) {
                float4 wv = *(const float4*)&sW[ic][kk][ocq];
#pragma unroll
                for (int j = 0; j < 4; j++) {
                    float iv = sIn[ic][oy * 2 + kk / 3][(oxl + j) * 2 + kk % 3];
                    acc[j][0] = fmaf(iv, wv.x, acc[j][0]);
                    acc[j][1] = fmaf(iv, wv.y, acc[j][1]);
                    acc[j][2] = fmaf(iv, wv.z, acc[j][2]);
                    acc[j][3] = fmaf(iv, wv.w, acc[j][3]);
                }
            }
        }
    }

#pragma unroll
    for (int j = 0; j < 4; j++)
#pragma unroll
        for (int q = 0; q < 4; q++) {
            int oc = oc0 + ocq + q;
            float v = acc[j][q] + b[oc];
            if (DO_GELU) v = gelu_tanh(v);
            out[((n * COUT + oc) * HOUT + oy0 + oy) * HOUT + ox0 + oxl + j] = v;
        }
}

// ---------------------------------------------------------------------------
// kproj: kprojT[m][c][k] = sum_d codebook[m][k][d] * wk[m][c][d]  (transposed)
// ---------------------------------------------------------------------------
__global__ __launch_bounds__(256) void kproj_kernel(
    const float* __restrict__ codebook, const float* __restrict__ wk)
{
    int idx = blockIdx.x * 256 + threadIdx.x;   // 65536 total
    int c = idx & 63;
    int k = (idx >> 6) & 255;
    int m = idx >> 14;
    const float* cb = codebook + (m * 256 + k) * 64;
    const float* wkp = wk + (m * 64 + c) * 64;
    float s = 0.0f;
#pragma unroll
    for (int d = 0; d < 64; d++) s = fmaf(cb[d], wkp[d], s);
    g_kprojT[(m * 64 + c) * 256 + k] = s;
}

// ---------------------------------------------------------------------------
// score v2: grid (pxtile=8, m=4, n=16) = 512 blocks, 256 threads.
// ---------------------------------------------------------------------------
__global__ __launch_bounds__(256) void score2_kernel(
    const float* __restrict__ wq, unsigned char* __restrict__ out_raw,
    int mode, int has_hw)
{
    __shared__ float qsT[64 * 36];      // [d][px]  (pad 36)
    __shared__ float qpT[64 * 36];      // [c][px]
    __shared__ float wqs[64 * 65];      // [c][d]   (pad 65)

    int t = threadIdx.x;
    int pt = blockIdx.x;                // 0..7 px tiles of 32
    int m = blockIdx.y;
    int n = blockIdx.z;

    for (int idx = t; idx < 64 * 32; idx += 256) {
        int d = idx >> 5, px = idx & 31;
        qsT[d * 36 + px] = g_buf4[(n * 256 + m * 64 + d) * 256 + pt * 32 + px];
    }
    for (int idx = t; idx < 4096; idx += 256) {
        int c = idx >> 6, d = idx & 63;
        wqs[c * 65 + d] = wq[(m * 64 + c) * 64 + d];
    }
    __syncthreads();

    {
        int c = t & 63, pxg = t >> 6;   // 4 groups of 8 px
        float a0 = 0, a1 = 0, a2 = 0, a3 = 0, a4 = 0, a5 = 0, a6 = 0, a7 = 0;
#pragma unroll 8
        for (int d = 0; d < 64; d++) {
            float wv = wqs[c * 65 + d];
            const float* qr = &qsT[d * 36 + pxg * 8];
            float4 qa = *(const float4*)qr;
            float4 qb = *(const float4*)(qr + 4);
            a0 = fmaf(wv, qa.x, a0); a1 = fmaf(wv, qa.y, a1);
            a2 = fmaf(wv, qa.z, a2); a3 = fmaf(wv, qa.w, a3);
            a4 = fmaf(wv, qb.x, a4); a5 = fmaf(wv, qb.y, a5);
            a6 = fmaf(wv, qb.z, a6); a7 = fmaf(wv, qb.w, a7);
        }
        float* qo = &qpT[c * 36 + pxg * 8];
        qo[0] = a0; qo[1] = a1; qo[2] = a2; qo[3] = a3;
        qo[4] = a4; qo[5] = a5; qo[6] = a6; qo[7] = a7;
    }
    __syncthreads();

    int px = t & 31, kgrp = t >> 5;     // 8 groups x 32 k
    int k0 = kgrp * 32;
    float acc[32];
#pragma unroll
    for (int k = 0; k < 32; k++) acc[k] = 0.0f;

    const float* kbase = g_kprojT + (m * 64) * 256 + k0;
    for (int c = 0; c < 64; c++) {
        float qv = qpT[c * 36 + px];
        const float4* kr = (const float4*)(kbase + c * 256);
#pragma unroll
        for (int v = 0; v < 8; v++) {
            float4 kv = __ldg(kr + v);
            acc[v * 4 + 0] = fmaf(qv, kv.x, acc[v * 4 + 0]);
            acc[v * 4 + 1] = fmaf(qv, kv.y, acc[v * 4 + 1]);
            acc[v * 4 + 2] = fmaf(qv, kv.z, acc[v * 4 + 2]);
            acc[v * 4 + 3] = fmaf(qv, kv.w, acc[v * 4 + 3]);
        }
    }

    float best = -3.402823466e38f;
    int bi = 0;
#pragma unroll
    for (int k = 0; k < 32; k++)
        if (acc[k] > best) { best = acc[k]; bi = k0 + k; }  // strict > = first max

    __syncthreads();
    float* redV = qsT;
    int* redI = (int*)(qsT + 256);
    redV[t] = best;
    redI[t] = bi;
    __syncthreads();

    if (t < 32) {
        float bv = redV[t];
        int bx = redI[t];
#pragma unroll
        for (int g = 1; g < 8; g++) {
            float v = redV[g * 32 + t];
            int i2 = redI[g * 32 + t];
            if (v > bv || (v == bv && i2 < bx)) { bv = v; bx = i2; }
        }
        int oidx = (n * 256 + pt * 32 + t) * 4 + m;
        if (mode == 0)      ((unsigned char*)out_raw)[oidx] = (unsigned char)bx;
        else if (mode == 1) ((int*)out_raw)[oidx] = bx;
        else                ((float*)out_raw)[oidx] = (float)bx;
    }
    if (blockIdx.x == 0 && blockIdx.y == 0 && blockIdx.z == 0 && t == 0 && has_hw) {
        if (mode == 0) {
            int* hw = (int*)(out_raw + 16384);
            hw[0] = 256; hw[1] = 256;
        } else if (mode == 1) {
            int* hw = (int*)out_raw;
            hw[16384] = 256; hw[16385] = 256;
        } else {
            float* hw = (float*)out_raw;
            hw[16384] = 256.0f; hw[16385] = 256.0f;
        }
    }
}

// ---------------------------------------------------------------------------
// launch
// ---------------------------------------------------------------------------
extern "C" void kernel_launch(void* const* d_in, const int* in_sizes, int n_in,
                              void* d_out, int out_size)
{
    // defensive input remap by element count
    int ix = 0, iw1 = 1, ib1 = 2, iw2 = 3, ib2 = 4, iw3 = 5, ib3 = 6,
        iw4 = 7, ib4 = 8, icb = 9, iwq = 10, iwk = 11;
    if (n_in == 12) {
        int p256[2] = {-1, -1}, np256 = 0;
        int p16k[2] = {-1, -1}, np16k = 0;
        int xpos = -1;
        for (int i = 0; i < 12; i++) {
            switch (in_sizes[i]) {
                case 3145728: ix = i; xpos = i; break;
                case 1728:    iw1 = i; break;
                case 64:      ib1 = i; break;
                case 73728:   iw2 = i; break;
                case 128:     ib2 = i; break;
                case 294912:  iw3 = i; break;
                case 589824:  iw4 = i; break;
                case 65536:   icb = i; break;
                case 256:     if (np256 < 2) p256[np256++] = i; break;
                case 16384:   if (np16k < 2) p16k[np16k++] = i; break;
                default: break;
            }
        }
        if (np256 == 2) { ib3 = p256[0]; ib4 = p256[1]; }
        if (np16k == 2) {
            if (xpos >= 0 && xpos < p16k[0]) { iwq = p16k[0]; iwk = p16k[1]; }
            else                             { iwk = p16k[0]; iwq = p16k[1]; }
        }
    }

    const float* x        = (const float*)d_in[ix];
    const float* w1       = (const float*)d_in[iw1];
    const float* b1       = (const float*)d_in[ib1];
    const float* w2       = (const float*)d_in[iw2];
    const float* b2       = (const float*)d_in[ib2];
    const float* w3       = (const float*)d_in[iw3];
    const float* b3       = (const float*)d_in[ib3];
    const float* w4       = (const float*)d_in[iw4];
    const float* b4       = (const float*)d_in[ib4];
    const float* codebook = (const float*)d_in[icb];
    const float* wq       = (const float*)d_in[iwq];
    const float* wk       = (const float*)d_in[iwk];

    float *buf1, *buf2, *buf3, *buf4;
    cudaGetSymbolAddress((void**)&buf1, g_buf1);
    cudaGetSymbolAddress((void**)&buf2, g_buf2);
    cudaGetSymbolAddress((void**)&buf3, g_buf3);
    cudaGetSymbolAddress((void**)&buf4, g_buf4);

    // convR16 dynamic smem: (16*17*34 + 16*9*64) * 4 = 73856 B
    const int SM16 = (16 * 17 * 34 + 16 * 9 * 64) * 4;
    cudaFuncSetAttribute(convR16_kernel<64, 128, 128, 64, true>,
                         cudaFuncAttributeMaxDynamicSharedMemorySize, SM16);
    cudaFuncSetAttribute(convR16_kernel<128, 256, 64, 32, true>,
                         cudaFuncAttributeMaxDynamicSharedMemorySize, SM16);

    // conv1: 256 tiles x 16 images
    conv1_kernel<<<dim3(256, 1, NIMG), 256>>>(x, w1, b1);
    // conv2: 64->128, 128->64; convR16 tiles (64/8)*(64/16)=32 x 2 ocb
    convR16_kernel<64, 128, 128, 64, true>
        <<<dim3(32, 2, NIMG), 256, SM16>>>(buf1, w2, b2, buf2);
    // conv3: 128->256, 64->32; convR16 tiles (32/8)*(32/16)=8 x 4 ocb
    convR16_kernel<128, 256, 64, 32, true>
        <<<dim3(8, 4, NIMG), 256, SM16>>>(buf2, w3, b3, buf3);
    // conv4: 256->256, 32->16; plain v1 (empirical floor), 4 x 4 ocb -> 256 CTAs
    conv_kernel<256, 256, 32, 16, false>
        <<<dim3(4, 4, NIMG), 256>>>(buf3, w4, b4, buf4);
    // kproj (transposed output)
    kproj_kernel<<<256, 256>>>(codebook, wk);

    int mode, has_hw;
    if (out_size == 16386)      { mode = 2; has_hw = 1; }
    else if (out_size >= 16392) { mode = 0; has_hw = 1; }
    else                        { mode = 0; has_hw = 0; }

    score2_kernel<<<dim3(8, 4, NIMG), 256>>>(wq, (unsigned char*)d_out,
                                             mode, has_hw);
}